// round 3
// baseline (speedup 1.0000x reference)
#include <cuda_runtime.h>
#include <math.h>

// Problem constants
#define BATCH 2
#define SEQ   4096
#define DEMB  768
#define DMLP  3072
#define NHEAD 12
#define DHEAD 64
#define MROWS (BATCH * SEQ)   // 8192
#define D3    (3 * DEMB)      // 2304

// ---------------------------------------------------------------------------
// Scratch (device globals; no allocation anywhere)
// ---------------------------------------------------------------------------
__device__ float g_ln1x[MROWS * DEMB];
__device__ float g_qkv [MROWS * D3];
__device__ float g_attn[MROWS * DEMB];
__device__ float g_x1  [MROWS * DEMB];
__device__ float g_ln2x[MROWS * DEMB];
__device__ float g_mlp [MROWS * DMLP];

// ---------------------------------------------------------------------------
// LayerNorm: one block per row of 768, 256 threads (3 elems/thread)
// ---------------------------------------------------------------------------
__global__ __launch_bounds__(256) void ln_kernel(
    const float* __restrict__ x, const float* __restrict__ g,
    const float* __restrict__ b, float* __restrict__ out)
{
    const int row = blockIdx.x;
    const int tid = threadIdx.x;
    const float* xr = x + (size_t)row * DEMB;

    float v0 = xr[tid], v1 = xr[tid + 256], v2 = xr[tid + 512];
    float s  = v0 + v1 + v2;
    float q  = v0 * v0 + v1 * v1 + v2 * v2;

    #pragma unroll
    for (int o = 16; o; o >>= 1) {
        s += __shfl_xor_sync(0xffffffffu, s, o);
        q += __shfl_xor_sync(0xffffffffu, q, o);
    }

    __shared__ float sh_s[8], sh_q[8], sh_mu, sh_r;
    if ((tid & 31) == 0) { sh_s[tid >> 5] = s; sh_q[tid >> 5] = q; }
    __syncthreads();
    if (tid == 0) {
        float ts = 0.f, tq = 0.f;
        #pragma unroll
        for (int i = 0; i < 8; i++) { ts += sh_s[i]; tq += sh_q[i]; }
        float mu  = ts * (1.0f / DEMB);
        float var = tq * (1.0f / DEMB) - mu * mu;
        sh_mu = mu;
        sh_r  = rsqrtf(var + 1e-5f);
    }
    __syncthreads();
    const float mu = sh_mu, r = sh_r;

    float* orow = out + (size_t)row * DEMB;
    orow[tid]       = (v0 - mu) * r * g[tid]       + b[tid];
    orow[tid + 256] = (v1 - mu) * r * g[tid + 256] + b[tid + 256];
    orow[tid + 512] = (v2 - mu) * r * g[tid + 512] + b[tid + 512];
}

// ---------------------------------------------------------------------------
// SGEMM: C[M,N] = A[M,K] @ B[K,N] (+ bias) (-> gelu) (+ residual)
// 128x128x16 tiles, 256 threads, 8x8 register tile per thread.
// epi bits: 1=bias, 2=gelu(exact erf), 4=residual add
// Requires M,N % 128 == 0, K % 16 == 0 (true for all calls here).
// ---------------------------------------------------------------------------
__global__ __launch_bounds__(256) void sgemm_kernel(
    const float* __restrict__ A, const float* __restrict__ B,
    const float* __restrict__ bias, const float* __restrict__ res,
    float* __restrict__ C, int M, int N, int K, int epi)
{
    __shared__ float As[16][128];   // A transposed: As[k][m]
    __shared__ float Bs[16][128];   // Bs[k][n]

    const int tid = threadIdx.x;
    const int bx = blockIdx.x, by = blockIdx.y;
    const int ty = tid >> 4, tx = tid & 15;

    float acc[8][8];
    #pragma unroll
    for (int i = 0; i < 8; i++)
        #pragma unroll
        for (int j = 0; j < 8; j++) acc[i][j] = 0.f;

    const float* Abase = A + (size_t)(by * 128) * K;
    const float* Bbase = B + bx * 128;

    for (int k0 = 0; k0 < K; k0 += 16) {
        #pragma unroll
        for (int l = 0; l < 2; l++) {
            int idx = tid + l * 256;
            int r  = idx >> 2, c4 = (idx & 3) << 2;
            float4 a = *(const float4*)(Abase + (size_t)r * K + k0 + c4);
            As[c4 + 0][r] = a.x; As[c4 + 1][r] = a.y;
            As[c4 + 2][r] = a.z; As[c4 + 3][r] = a.w;
            int rb = idx >> 5, cb = (idx & 31) << 2;
            *(float4*)&Bs[rb][cb] = *(const float4*)(Bbase + (size_t)(k0 + rb) * N + cb);
        }
        __syncthreads();
        #pragma unroll
        for (int k = 0; k < 16; k++) {
            float4 a0 = *(const float4*)&As[k][ty * 8];
            float4 a1 = *(const float4*)&As[k][ty * 8 + 4];
            float4 b0 = *(const float4*)&Bs[k][tx * 8];
            float4 b1 = *(const float4*)&Bs[k][tx * 8 + 4];
            float ra[8] = {a0.x, a0.y, a0.z, a0.w, a1.x, a1.y, a1.z, a1.w};
            float rb[8] = {b0.x, b0.y, b0.z, b0.w, b1.x, b1.y, b1.z, b1.w};
            #pragma unroll
            for (int i = 0; i < 8; i++)
                #pragma unroll
                for (int j = 0; j < 8; j++)
                    acc[i][j] = fmaf(ra[i], rb[j], acc[i][j]);
        }
        __syncthreads();
    }

    const int row0 = by * 128 + ty * 8;
    const int col0 = bx * 128 + tx * 8;
    float bv[8];
    #pragma unroll
    for (int j = 0; j < 8; j++) bv[j] = (epi & 1) ? bias[col0 + j] : 0.f;

    #pragma unroll
    for (int i = 0; i < 8; i++) {
        size_t off = (size_t)(row0 + i) * N + col0;
        float o[8];
        #pragma unroll
        for (int j = 0; j < 8; j++) {
            float v = acc[i][j] + bv[j];
            if (epi & 2) v = 0.5f * v * (1.0f + erff(v * 0.70710678118654752f));
            o[j] = v;
        }
        if (epi & 4) {
            float4 r0 = *(const float4*)(res + off);
            float4 r1 = *(const float4*)(res + off + 4);
            o[0] += r0.x; o[1] += r0.y; o[2] += r0.z; o[3] += r0.w;
            o[4] += r1.x; o[5] += r1.y; o[6] += r1.z; o[7] += r1.w;
        }
        *(float4*)(C + off)     = make_float4(o[0], o[1], o[2], o[3]);
        *(float4*)(C + off + 4) = make_float4(o[4], o[5], o[6], o[7]);
    }
}

// ---------------------------------------------------------------------------
// Flash attention (causal). One block per (q_tile=64 rows, head, batch).
// 256 threads as a 16x16 grid; each thread owns a 4x4 S / O sub-tile.
// KV tiles of 64 rows, online softmax, diagonal early exit.
// Dynamic smem: sQ/sK/sV/sP = 4 * 64 * 65 floats = 66560 B.
// ---------------------------------------------------------------------------
__global__ __launch_bounds__(256) void attn_kernel(
    const float* __restrict__ qkv, float* __restrict__ y)
{
    // Reverse q-tile order so the biggest tiles (most KV steps) launch first.
    const int qt = gridDim.x - 1 - (int)blockIdx.x;
    const int h  = blockIdx.y;
    const int b  = blockIdx.z;

    const float* base = qkv + (size_t)b * SEQ * D3;
    const float* Qp = base + h * DHEAD;
    const float* Kp = base + DEMB + h * DHEAD;
    const float* Vp = base + 2 * DEMB + h * DHEAD;

    extern __shared__ float sm[];
    float (*sQ)[65] = (float(*)[65])(sm);
    float (*sK)[65] = (float(*)[65])(sm + 64 * 65);
    float (*sV)[65] = (float(*)[65])(sm + 2 * 64 * 65);
    float (*sP)[65] = (float(*)[65])(sm + 3 * 64 * 65);

    const int tid = threadIdx.x;
    const int ty = tid >> 4, tx = tid & 15;

    // Load Q tile (64 x 64)
    #pragma unroll
    for (int l = 0; l < 4; l++) {
        int idx = tid + l * 256;
        int r = idx >> 4, c = (idx & 15) << 2;
        float4 v = *(const float4*)(Qp + (size_t)(qt * 64 + r) * D3 + c);
        sQ[r][c] = v.x; sQ[r][c + 1] = v.y; sQ[r][c + 2] = v.z; sQ[r][c + 3] = v.w;
    }

    float m[4], lsum[4], acc[4][4];
    #pragma unroll
    for (int i = 0; i < 4; i++) {
        m[i] = -INFINITY; lsum[i] = 0.f;
        #pragma unroll
        for (int j = 0; j < 4; j++) acc[i][j] = 0.f;
    }

    for (int kt = 0; kt <= qt; kt++) {
        __syncthreads();   // protect sK/sV (read in previous PV) before reload
        #pragma unroll
        for (int l = 0; l < 4; l++) {
            int idx = tid + l * 256;
            int r = idx >> 4, c = (idx & 15) << 2;
            float4 kv = *(const float4*)(Kp + (size_t)(kt * 64 + r) * D3 + c);
            sK[r][c] = kv.x; sK[r][c + 1] = kv.y; sK[r][c + 2] = kv.z; sK[r][c + 3] = kv.w;
            float4 vv = *(const float4*)(Vp + (size_t)(kt * 64 + r) * D3 + c);
            sV[r][c] = vv.x; sV[r][c + 1] = vv.y; sV[r][c + 2] = vv.z; sV[r][c + 3] = vv.w;
        }
        __syncthreads();

        // S = Q @ K^T
        float s[4][4];
        #pragma unroll
        for (int i = 0; i < 4; i++)
            #pragma unroll
            for (int j = 0; j < 4; j++) s[i][j] = 0.f;
        #pragma unroll 8
        for (int k = 0; k < 64; k++) {
            float qa[4], kb[4];
            #pragma unroll
            for (int i = 0; i < 4; i++) qa[i] = sQ[ty * 4 + i][k];
            #pragma unroll
            for (int j = 0; j < 4; j++) kb[j] = sK[tx * 4 + j][k];
            #pragma unroll
            for (int i = 0; i < 4; i++)
                #pragma unroll
                for (int j = 0; j < 4; j++)
                    s[i][j] = fmaf(qa[i], kb[j], s[i][j]);
        }

        // scale + causal mask (only diagonal tile is partial) + row max
        const bool diag = (kt == qt);
        float tmax[4];
        #pragma unroll
        for (int i = 0; i < 4; i++) {
            float mx = -INFINITY;
            #pragma unroll
            for (int j = 0; j < 4; j++) {
                float v = s[i][j] * 0.125f;   // 1/sqrt(64)
                if (diag && (tx * 4 + j) > (ty * 4 + i)) v = -INFINITY;
                s[i][j] = v;
                mx = fmaxf(mx, v);
            }
            tmax[i] = mx;
        }
        #pragma unroll
        for (int o = 8; o; o >>= 1)
            #pragma unroll
            for (int i = 0; i < 4; i++)
                tmax[i] = fmaxf(tmax[i], __shfl_xor_sync(0xffffffffu, tmax[i], o));

        // online softmax update
        float alpha[4];
        #pragma unroll
        for (int i = 0; i < 4; i++) {
            float mn = fmaxf(m[i], tmax[i]);
            alpha[i] = __expf(m[i] - mn);   // exp(-inf)=+0 on first tile
            m[i] = mn;
        }
        float rsum[4];
        #pragma unroll
        for (int i = 0; i < 4; i++) {
            float rs = 0.f;
            #pragma unroll
            for (int j = 0; j < 4; j++) {
                float p = __expf(s[i][j] - m[i]);
                s[i][j] = p;
                rs += p;
            }
            rsum[i] = rs;
        }
        #pragma unroll
        for (int o = 8; o; o >>= 1)
            #pragma unroll
            for (int i = 0; i < 4; i++)
                rsum[i] += __shfl_xor_sync(0xffffffffu, rsum[i], o);

        #pragma unroll
        for (int i = 0; i < 4; i++) {
            lsum[i] = lsum[i] * alpha[i] + rsum[i];
            #pragma unroll
            for (int j = 0; j < 4; j++) {
                sP[ty * 4 + i][tx * 4 + j] = s[i][j];
                acc[i][j] *= alpha[i];
            }
        }
        __syncthreads();

        // O += P @ V
        #pragma unroll 8
        for (int c = 0; c < 64; c++) {
            float pa[4], vb[4];
            #pragma unroll
            for (int i = 0; i < 4; i++) pa[i] = sP[ty * 4 + i][c];
            #pragma unroll
            for (int j = 0; j < 4; j++) vb[j] = sV[c][tx * 4 + j];
            #pragma unroll
            for (int i = 0; i < 4; i++)
                #pragma unroll
                for (int j = 0; j < 4; j++)
                    acc[i][j] = fmaf(pa[i], vb[j], acc[i][j]);
        }
    }

    // write O / l  to y[b, t, h*64 + d]
    #pragma unroll
    for (int i = 0; i < 4; i++) {
        float inv = 1.0f / lsum[i];
        int r = qt * 64 + ty * 4 + i;
        float* yr = y + (size_t)(b * SEQ + r) * DEMB + h * DHEAD + tx * 4;
        *(float4*)yr = make_float4(acc[i][0] * inv, acc[i][1] * inv,
                                   acc[i][2] * inv, acc[i][3] * inv);
    }
}

// ---------------------------------------------------------------------------
// Launch
// ---------------------------------------------------------------------------
extern "C" void kernel_launch(void* const* d_in, const int* in_sizes, int n_in,
                              void* d_out, int out_size)
{
    (void)in_sizes; (void)n_in; (void)out_size;
    const float* x    = (const float*)d_in[0];
    const float* ln1g = (const float*)d_in[1];
    const float* ln1b = (const float*)d_in[2];
    const float* wqkv = (const float*)d_in[3];
    const float* wo_w = (const float*)d_in[4];
    const float* wo_b = (const float*)d_in[5];
    const float* ln2g = (const float*)d_in[6];
    const float* ln2b = (const float*)d_in[7];
    const float* w1w  = (const float*)d_in[8];
    const float* w1b  = (const float*)d_in[9];
    const float* w2w  = (const float*)d_in[10];
    const float* w2b  = (const float*)d_in[11];
    float* out = (float*)d_out;

    float *ln1x, *qkvp, *attnp, *x1p, *ln2x, *mlpp;
    cudaGetSymbolAddress((void**)&ln1x,  g_ln1x);
    cudaGetSymbolAddress((void**)&qkvp,  g_qkv);
    cudaGetSymbolAddress((void**)&attnp, g_attn);
    cudaGetSymbolAddress((void**)&x1p,   g_x1);
    cudaGetSymbolAddress((void**)&ln2x,  g_ln2x);
    cudaGetSymbolAddress((void**)&mlpp,  g_mlp);

    const int ATTN_SMEM = 4 * 64 * 65 * (int)sizeof(float);  // 66560 B
    cudaFuncSetAttribute((const void*)attn_kernel,
                         cudaFuncAttributeMaxDynamicSharedMemorySize, ATTN_SMEM);

    // ln1
    ln_kernel<<<MROWS, 256>>>(x, ln1g, ln1b, ln1x);
    // qkv = ln1x @ wqkv  [8192 x 2304]
    sgemm_kernel<<<dim3(D3 / 128, MROWS / 128), 256>>>(
        ln1x, wqkv, nullptr, nullptr, qkvp, MROWS, D3, DEMB, 0);
    // attention
    attn_kernel<<<dim3(SEQ / 64, NHEAD, BATCH), 256, ATTN_SMEM>>>(qkvp, attnp);
    // x1 = x + attn @ wo_w + wo_b
    sgemm_kernel<<<dim3(DEMB / 128, MROWS / 128), 256>>>(
        attnp, wo_w, wo_b, x, x1p, MROWS, DEMB, DEMB, 1 | 4);
    // ln2
    ln_kernel<<<MROWS, 256>>>(x1p, ln2g, ln2b, ln2x);
    // h = gelu(ln2x @ w1 + b1)  [8192 x 3072]
    sgemm_kernel<<<dim3(DMLP / 128, MROWS / 128), 256>>>(
        ln2x, w1w, w1b, nullptr, mlpp, MROWS, DMLP, DEMB, 1 | 2);
    // out = x1 + h @ w2 + b2
    sgemm_kernel<<<dim3(DEMB / 128, MROWS / 128), 256>>>(
        mlpp, w2w, w2b, x1p, out, MROWS, DEMB, DMLP, 1 | 4);
}